// round 7
// baseline (speedup 1.0000x reference)
#include <cuda_runtime.h>
#include <cuda_bf16.h>
#include <math.h>
#include <stdint.h>
#include <stddef.h>

// ------------ problem constants ------------
#define Bsz   2048
#define Nn    20
#define Dd    512
#define Hh    8
#define Mrows (Bsz*Nn)     // 40960
#define K3    (3*Dd)       // 1536

// ------------ scratch (static __device__) ------------
__device__ __align__(256) float g_conv[(size_t)Mrows * K3];        // conv GEMM out (fp32)
__device__ __align__(256) float g_qp[(size_t)Mrows * Hh];
__device__ __align__(256) __nv_bfloat16 g_xh[(size_t)Mrows * Dd];  // x split hi/lo
__device__ __align__(256) __nv_bfloat16 g_xl[(size_t)Mrows * Dd];
__device__ __align__(256) __nv_bfloat16 g_ah[(size_t)Mrows * Dd];  // attn out split
__device__ __align__(256) __nv_bfloat16 g_al[(size_t)Mrows * Dd];
__device__ __align__(256) __nv_bfloat16 g_wth[(size_t)K3 * K3];    // W^T concat [oc][kk]
__device__ __align__(256) __nv_bfloat16 g_wtl[(size_t)K3 * K3];
__device__ __align__(256) __nv_bfloat16 g_woh[(size_t)Dd * Dd];    // Wo^T [n][k]
__device__ __align__(256) __nv_bfloat16 g_wol[(size_t)Dd * Dd];

// ------------ small PTX helpers (plain-sm_103-safe) ------------
__device__ __forceinline__ uint32_t smem_u32(const void* p) {
    uint32_t a;
    asm("{ .reg .u64 t; cvta.to.shared.u64 t, %1; cvt.u32.u64 %0, t; }" : "=r"(a) : "l"(p));
    return a;
}
__device__ __forceinline__ void cp_async16(uint32_t saddr, const void* gaddr, uint32_t srcsize) {
    asm volatile("cp.async.cg.shared.global [%0], [%1], 16, %2;"
                 :: "r"(saddr), "l"(gaddr), "r"(srcsize) : "memory");
}
__device__ __forceinline__ void cp_commit() { asm volatile("cp.async.commit_group;" ::: "memory"); }
__device__ __forceinline__ void cp_wait0()  { asm volatile("cp.async.wait_group 0;" ::: "memory"); }
__device__ __forceinline__ void cp_wait1()  { asm volatile("cp.async.wait_group 1;" ::: "memory"); }

__device__ __forceinline__ void ldsm4(uint32_t* r, uint32_t addr) {
    asm volatile("ldmatrix.sync.aligned.m8n8.x4.shared.b16 {%0,%1,%2,%3}, [%4];"
                 : "=r"(r[0]), "=r"(r[1]), "=r"(r[2]), "=r"(r[3]) : "r"(addr));
}
__device__ __forceinline__ void mma16816(float* c, const uint32_t* a, const uint32_t* b) {
    asm volatile("mma.sync.aligned.m16n8k16.row.col.f32.bf16.bf16.f32 "
                 "{%0,%1,%2,%3}, {%4,%5,%6,%7}, {%8,%9}, {%0,%1,%2,%3};"
                 : "+f"(c[0]), "+f"(c[1]), "+f"(c[2]), "+f"(c[3])
                 : "r"(a[0]), "r"(a[1]), "r"(a[2]), "r"(a[3]), "r"(b[0]), "r"(b[1]));
}

// ============================================================
// precompute kernels
// ============================================================
__global__ void split_x(const float* __restrict__ x) {
    size_t i = (size_t)blockIdx.x * 256 + threadIdx.x;
    if (i >= (size_t)Mrows * Dd) return;
    float v = x[i];
    __nv_bfloat16 h = __float2bfloat16(v);
    g_xh[i] = h;
    g_xl[i] = __float2bfloat16(v - __bfloat162float(h));
}

__global__ void repack_w(const float* __restrict__ Wq,
                         const float* __restrict__ Wk,
                         const float* __restrict__ Wv) {
    size_t idx = (size_t)blockIdx.x * 256 + threadIdx.x;
    if (idx >= (size_t)K3 * K3) return;
    int oc = (int)(idx / K3);
    int kk = (int)(idx - (size_t)oc * K3);
    int t = kk >> 9, i = kk & 511;
    int p = oc >> 9, o = oc & 511;
    const float* W = (p == 0) ? Wq : (p == 1) ? Wk : Wv;
    float v = W[(size_t)o * K3 + i * 3 + t];
    __nv_bfloat16 h = __float2bfloat16(v);
    g_wth[idx] = h;
    g_wtl[idx] = __float2bfloat16(v - __bfloat162float(h));
}

__global__ void repack_wo(const float* __restrict__ Wo) {
    int idx = blockIdx.x * 256 + threadIdx.x;
    if (idx >= Dd * Dd) return;
    int n = idx >> 9, k = idx & 511;
    float v = Wo[(size_t)k * Dd + n];
    __nv_bfloat16 h = __float2bfloat16(v);
    g_woh[idx] = h;
    g_wol[idx] = __float2bfloat16(v - __bfloat162float(h));
}

// ============================================================
// warp-mma bf16 GEMM: C = A * B^T (B stored [N x K]); bf16x3 split.
// MODE 1: A gathered via im2col of x.
// CTA 128x128, 512 thr (16 warps 2x8), warp tile 64x16, BK=32,
// 3-stage cp.async pipeline, one __syncthreads per K-iter.
// smem rows: 32 data + 8 pad = 40 elems (80B) -> conflict-free ldmatrix.
// ============================================================
#define LDS_E 40
#define TILE_E (128 * LDS_E)
#define TILE_BYTES (TILE_E * 2)          // 10240 B
#define STAGE_BYTES (4 * TILE_BYTES)     // 40960 B
#define GEMM_SMEM (3 * STAGE_BYTES)      // 122880 B

template<int MODE, bool BIAS>
__global__ __launch_bounds__(512, 1)
void tc_gemm(const __nv_bfloat16* __restrict__ Ah, const __nv_bfloat16* __restrict__ Al,
             const __nv_bfloat16* __restrict__ Bh, const __nv_bfloat16* __restrict__ Bl,
             float* __restrict__ C, const float* __restrict__ bias, int K, int N)
{
    extern __shared__ __nv_bfloat16 smem[];
    const uint32_t sb = smem_u32(smem);
    const int tid = threadIdx.x;
    const int wid = tid >> 5, lid = tid & 31;
    const int warp_m = wid >> 3;      // 0..1  (64 rows)
    const int warp_n = wid & 7;       // 0..7  (16 cols)
    const int m0 = blockIdx.y * 128, n0 = blockIdx.x * 128;
    const int NC = K >> 5;

    // one 16B chunk per tile per thread per stage
    const int lr = tid >> 2;          // row 0..127
    const int lq = tid & 3;           // quad 0..3 (8 elems each)
    const uint32_t lsoff = (uint32_t)(lr * LDS_E + lq * 8) * 2;

    auto load_stage = [&](int c) {
        const uint32_t sbase = sb + (uint32_t)(c % 3) * STAGE_BYTES;
        const int kk0 = c << 5;
        // A (hi & lo)
        size_t aoff; uint32_t vsz = 16;
        if (MODE == 1) {
            int gm = m0 + lr;
            int bb = gm / Nn, nn = gm - bb * Nn;
            int t = kk0 >> 9;
            int d = (kk0 & 511) + lq * 8;
            int jj = nn + t - 1;
            if (jj < 0 || jj >= Nn) { vsz = 0; jj = 0; }
            aoff = ((size_t)(bb * Nn + jj) << 9) + d;
        } else {
            aoff = (size_t)(m0 + lr) * K + kk0 + lq * 8;
        }
        cp_async16(sbase + 0 * TILE_BYTES + lsoff, Ah + aoff, vsz);
        cp_async16(sbase + 1 * TILE_BYTES + lsoff, Al + aoff, vsz);
        size_t boff = (size_t)(n0 + lr) * K + kk0 + lq * 8;
        cp_async16(sbase + 2 * TILE_BYTES + lsoff, Bh + boff, 16);
        cp_async16(sbase + 3 * TILE_BYTES + lsoff, Bl + boff, 16);
        cp_commit();
    };

    float acc[4][2][4];
    #pragma unroll
    for (int i = 0; i < 4; i++)
        #pragma unroll
        for (int j = 0; j < 2; j++)
            #pragma unroll
            for (int e = 0; e < 4; e++) acc[i][j][e] = 0.f;

    load_stage(0);
    load_stage(1);

    // ldmatrix lane addressing (byte units within a [128][40] tile)
    const uint32_t a_row  = (uint32_t)(warp_m * 64 + (lid & 15));
    const uint32_t a_koff = (uint32_t)((lid >> 4) * 16);
    const uint32_t b_row  = (uint32_t)(warp_n * 16 + ((lid >> 4) * 8) + (lid & 7));
    const uint32_t b_koff = (uint32_t)(((lid >> 3) & 1) * 16);

    for (int c = 0; c < NC; c++) {
        if (c + 1 < NC) cp_wait1(); else cp_wait0();
        __syncthreads();
        if (c + 2 < NC) load_stage(c + 2);   // reuses buffer consumed at iter c-1

        const uint32_t sbase = sb + (uint32_t)(c % 3) * STAGE_BYTES;
        const uint32_t tAh = sbase + 0 * TILE_BYTES;
        const uint32_t tAl = sbase + 1 * TILE_BYTES;
        const uint32_t tBh = sbase + 2 * TILE_BYTES;
        const uint32_t tBl = sbase + 3 * TILE_BYTES;

        #pragma unroll
        for (int ks = 0; ks < 2; ks++) {
            const uint32_t kb = (uint32_t)(ks * 32);
            uint32_t fah[4][4], fal[4][4], fbh[4], fbl[4];
            #pragma unroll
            for (int ma = 0; ma < 4; ma++) {
                uint32_t ao = ((a_row + ma * 16) * LDS_E) * 2 + a_koff + kb;
                ldsm4(fah[ma], tAh + ao);
                ldsm4(fal[ma], tAl + ao);
            }
            {
                uint32_t bo = (b_row * LDS_E) * 2 + b_koff + kb;
                ldsm4(fbh, tBh + bo);
                ldsm4(fbl, tBl + bo);
            }
            #pragma unroll
            for (int ma = 0; ma < 4; ma++) {
                #pragma unroll
                for (int na = 0; na < 2; na++) {
                    mma16816(acc[ma][na], fah[ma], &fbh[na * 2]);
                    mma16816(acc[ma][na], fah[ma], &fbl[na * 2]);
                    mma16816(acc[ma][na], fal[ma], &fbh[na * 2]);
                }
            }
        }
    }

    // ---- epilogue ----
    const int mrow = m0 + warp_m * 64 + (lid >> 2);
    const int ncol = n0 + warp_n * 16 + (lid & 3) * 2;
    #pragma unroll
    for (int ma = 0; ma < 4; ma++) {
        #pragma unroll
        for (int na = 0; na < 2; na++) {
            int cc = ncol + na * 8;
            float b0 = 0.f, b1 = 0.f;
            if (BIAS) { b0 = bias[cc]; b1 = bias[cc + 1]; }
            float2 v0 = make_float2(acc[ma][na][0] + b0, acc[ma][na][1] + b1);
            float2 v1 = make_float2(acc[ma][na][2] + b0, acc[ma][na][3] + b1);
            *(float2*)(C + (size_t)(mrow + ma * 16)     * N + cc) = v0;
            *(float2*)(C + (size_t)(mrow + ma * 16 + 8) * N + cc) = v1;
        }
    }
}

// ============================================================
// qp[b,n,h] = tanh(x @ Wqf + bqf) @ Wqp (dyn bias factorization)
// ============================================================
__global__ __launch_bounds__(64)
void qp_kernel(const float* __restrict__ x, const float* __restrict__ Wqf,
               const float* __restrict__ bqf, const float* __restrict__ Wqp)
{
    __shared__ float xs[8][512];
    __shared__ float qf[8][64];
    int m0 = blockIdx.x * 8;
    int tid = threadIdx.x;

    for (int i = tid; i < 8 * 512; i += 64)
        xs[i >> 9][i & 511] = x[(size_t)m0 * 512 + i];
    __syncthreads();

    float acc[8];
    float bq = bqf[tid];
    #pragma unroll
    for (int r = 0; r < 8; r++) acc[r] = bq;
    for (int i = 0; i < 512; i++) {
        float w = Wqf[i * 64 + tid];
        #pragma unroll
        for (int r = 0; r < 8; r++) acc[r] += xs[r][i] * w;
    }
    #pragma unroll
    for (int r = 0; r < 8; r++) qf[r][tid] = tanhf(acc[r]);
    __syncthreads();

    int r = tid >> 3, h = tid & 7;
    float a = 0.f;
    #pragma unroll
    for (int t = 0; t < 64; t++) a += qf[r][t] * Wqp[t * 8 + h];
    g_qp[(size_t)(m0 + r) * 8 + h] = a;
}

// ============================================================
// Fused LayerNorm+residual + attention, one block per batch b.
// smem: buf[3][20][513] (q,k,v after LN+res), scores, bias tables.
// ============================================================
#define LNROW 513
#define SM_BUF   (3 * Nn * LNROW)             // 30780 floats
#define SM_SC    (SM_BUF)                     // + 8*20*20 = 3200
#define SM_REL   (SM_SC + Hh * Nn * Nn)       // + 8*39 = 312
#define SM_QPH   (SM_REL + Hh * (2 * Nn - 1)) // + 20*8 = 160
#define FUSED_SMEM_F (SM_QPH + Nn * Hh)       // 34452 floats
#define FUSED_SMEM (FUSED_SMEM_F * 4)         // 137808 bytes

__global__ __launch_bounds__(512, 1)
void ln_attn_kernel(const float* __restrict__ xin,
                    const float* __restrict__ gq_g, const float* __restrict__ gq_b,
                    const float* __restrict__ gk_g, const float* __restrict__ gk_b,
                    const float* __restrict__ gv_g, const float* __restrict__ gv_b,
                    const float* __restrict__ rel_table,
                    const float* __restrict__ gsb,
                    const float* __restrict__ alpha_p,
                    const float* __restrict__ bqp)
{
    extern __shared__ float sm[];
    float* buf  = sm;                 // [3][20][513]
    float* sc   = sm + SM_SC;         // [8][20][20]
    float* relh = sm + SM_REL;        // [8][39]
    float* qph  = sm + SM_QPH;        // [20][8]

    const int b = blockIdx.x;
    const int tid = threadIdx.x;
    const int wid = tid >> 5, lid = tid & 31;

    // ---- 1. load conv out into buf ----
    for (int i = tid; i < 3 * Nn * Dd; i += 512) {
        int p = i / (Nn * Dd);
        int rem = i - p * Nn * Dd;
        int n = rem >> 9, d = rem & 511;
        buf[(p * Nn + n) * LNROW + d] =
            g_conv[(size_t)(b * Nn + n) * K3 + p * Dd + d];
    }
    // bias tables
    if (tid < Hh * (2 * Nn - 1)) relh[tid] = rel_table[(tid % (2 * Nn - 1)) * Hh + (tid / (2 * Nn - 1))];
    else if (tid >= 480 && tid < 480 + Nn) {
        int n = tid - 480;
        #pragma unroll
        for (int h = 0; h < Hh; h++)
            qph[n * Hh + h] = g_qp[(size_t)(b * Nn + n) * Hh + h];
    }
    __syncthreads();

    // ---- 2. LayerNorm + residual, in place. 60 rows over 16 warps ----
    for (int r = wid; r < 3 * Nn; r += 16) {
        int p = r / Nn, n = r - p * Nn;
        float* row = buf + r * LNROW;
        float s = 0.f, sq = 0.f;
        #pragma unroll
        for (int j = 0; j < 16; j++) {
            float v = row[lid + j * 32];
            s += v; sq += v * v;
        }
        #pragma unroll
        for (int o = 16; o > 0; o >>= 1) {
            s  += __shfl_xor_sync(0xffffffffu, s,  o);
            sq += __shfl_xor_sync(0xffffffffu, sq, o);
        }
        float mean = s * (1.f / 512.f);
        float var  = sq * (1.f / 512.f) - mean * mean;
        float rstd = rsqrtf(var + 1e-5f);
        const float* g  = (p == 0) ? gq_g : (p == 1) ? gk_g : gv_g;
        const float* be = (p == 0) ? gq_b : (p == 1) ? gk_b : gv_b;
        const float* xr = xin + (size_t)(b * Nn + n) * Dd;
        #pragma unroll
        for (int j = 0; j < 16; j++) {
            int d = lid + j * 32;
            row[d] = xr[d] + (row[d] - mean) * rstd * g[d] + be[d];
        }
    }
    __syncthreads();

    // ---- 3. scores: tasks (h,n,m) ----
    const float alpha = *alpha_p;
    const float* q = buf;                      // p=0
    const float* k = buf + Nn * LNROW;         // p=1
    const float* v = buf + 2 * Nn * LNROW;     // p=2
    for (int t = tid; t < Hh * Nn * Nn; t += 512) {
        int h = t / (Nn * Nn);
        int rem = t - h * Nn * Nn;
        int n = rem / Nn, m = rem - n * Nn;
        const float* qr = q + n * LNROW + h * 64;
        const float* kr = k + m * LNROW + h * 64;
        float a = 0.f;
        #pragma unroll
        for (int d = 0; d < 64; d++) a += qr[d] * kr[d];
        a = a * 0.125f
          + relh[h * (2 * Nn - 1) + n - m + Nn - 1]
          + alpha * gsb[(size_t)(h * Nn + n) * Nn + m]
          + (qph[n * Hh + h] - qph[m * Hh + h]) + bqp[h];
        sc[t] = a;
    }
    __syncthreads();

    // ---- 4. softmax: 160 rows, one per thread ----
    if (tid < Hh * Nn) {
        float* row = sc + tid * Nn;
        float mx = -1e30f;
        #pragma unroll
        for (int m = 0; m < Nn; m++) mx = fmaxf(mx, row[m]);
        float s = 0.f;
        #pragma unroll
        for (int m = 0; m < Nn; m++) { float e = expf(row[m] - mx); row[m] = e; s += e; }
        float inv = 1.f / s;
        #pragma unroll
        for (int m = 0; m < Nn; m++) row[m] *= inv;
    }
    __syncthreads();

    // ---- 5. out = attn @ v, write bf16 hi/lo ----
    for (int t = tid; t < Hh * Nn * 64; t += 512) {
        int hn = t >> 6, d = t & 63;
        int h = hn / Nn, n = hn - h * Nn;
        const float* ar = sc + (h * Nn + n) * Nn;
        const float* vb = v + h * 64 + d;
        float a = 0.f;
        #pragma unroll
        for (int m = 0; m < Nn; m++) a += ar[m] * vb[m * LNROW];
        size_t dst = (size_t)(b * Nn + n) * Dd + h * 64 + d;
        __nv_bfloat16 hi = __float2bfloat16(a);
        g_ah[dst] = hi;
        g_al[dst] = __float2bfloat16(a - __bfloat162float(hi));
    }
}

// ============================================================
// launch
// ============================================================
extern "C" void kernel_launch(void* const* d_in, const int* in_sizes, int n_in,
                              void* d_out, int out_size)
{
    const float* x         = (const float*)d_in[0];
    const float* Wq        = (const float*)d_in[1];
    const float* Wk        = (const float*)d_in[2];
    const float* Wv        = (const float*)d_in[3];
    const float* gq_g      = (const float*)d_in[4];
    const float* gq_b      = (const float*)d_in[5];
    const float* gk_g      = (const float*)d_in[6];
    const float* gk_b      = (const float*)d_in[7];
    const float* gv_g      = (const float*)d_in[8];
    const float* gv_b      = (const float*)d_in[9];
    const float* rel_table = (const float*)d_in[10];
    const float* gsb       = (const float*)d_in[11];
    const float* alpha     = (const float*)d_in[12];
    const float* Wqf       = (const float*)d_in[13];
    const float* bqf       = (const float*)d_in[14];
    const float* Wqp       = (const float*)d_in[15];
    const float* bqp       = (const float*)d_in[16];
    const float* Wo        = (const float*)d_in[17];
    const float* bo        = (const float*)d_in[18];

    cudaFuncSetAttribute(tc_gemm<1, false>, cudaFuncAttributeMaxDynamicSharedMemorySize, GEMM_SMEM);
    cudaFuncSetAttribute(tc_gemm<0, true>,  cudaFuncAttributeMaxDynamicSharedMemorySize, GEMM_SMEM);
    cudaFuncSetAttribute(ln_attn_kernel,    cudaFuncAttributeMaxDynamicSharedMemorySize, FUSED_SMEM);

    __nv_bfloat16 *pxh, *pxl, *pwth, *pwtl, *pah, *pal, *pwoh, *pwol;
    float *pConv;
    cudaGetSymbolAddress((void**)&pxh, g_xh);
    cudaGetSymbolAddress((void**)&pxl, g_xl);
    cudaGetSymbolAddress((void**)&pwth, g_wth);
    cudaGetSymbolAddress((void**)&pwtl, g_wtl);
    cudaGetSymbolAddress((void**)&pah, g_ah);
    cudaGetSymbolAddress((void**)&pal, g_al);
    cudaGetSymbolAddress((void**)&pwoh, g_woh);
    cudaGetSymbolAddress((void**)&pwol, g_wol);
    cudaGetSymbolAddress((void**)&pConv, g_conv);

    // 1. precompute bf16 hi/lo splits
    split_x<<<(Mrows * Dd + 255) / 256, 256>>>(x);
    repack_w<<<(K3 * K3 + 255) / 256, 256>>>(Wq, Wk, Wv);
    repack_wo<<<(Dd * Dd + 255) / 256, 256>>>(Wo);

    // 2. fused QKV conv as im2col GEMM: [40960 x 1536] = im2col(x) @ Wcat
    {
        dim3 grid(K3 / 128, Mrows / 128);   // (12, 320)
        tc_gemm<1, false><<<grid, 512, GEMM_SMEM>>>(pxh, pxl, pwth, pwtl,
                                                    pConv, nullptr, K3, K3);
    }

    // 3. dynamic-bias projection qp
    qp_kernel<<<Mrows / 8, 64>>>(x, Wqf, bqf, Wqp);

    // 4. fused LN+residual + attention (per batch), emits bf16 hi/lo
    ln_attn_kernel<<<Bsz, 512, FUSED_SMEM>>>(x, gq_g, gq_b, gk_g, gk_b, gv_g, gv_b,
                                             rel_table, gsb, alpha, bqp);

    // 5. output projection: [40960 x 512] @ Wo + bo
    {
        dim3 grid(Dd / 128, Mrows / 128);   // (4, 320)
        tc_gemm<0, true><<<grid, 512, GEMM_SMEM>>>(pah, pal, pwoh, pwol,
                                                   (float*)d_out, bo, Dd, Dd);
    }
}

// round 8
// speedup vs baseline: 1.7873x; 1.7873x over previous
#include <cuda_runtime.h>
#include <cuda_bf16.h>
#include <math.h>
#include <stdint.h>
#include <stddef.h>

// ------------ problem constants ------------
#define Bsz   2048
#define Nn    20
#define Dd    512
#define Hh    8
#define Mrows (Bsz*Nn)     // 40960
#define K3    (3*Dd)       // 1536

// ------------ scratch (static __device__) ------------
__device__ __align__(256) float g_conv[(size_t)Mrows * K3];        // conv GEMM out (fp32)
__device__ __align__(256) float g_qp[(size_t)Mrows * Hh];
__device__ __align__(256) __nv_bfloat16 g_xh[(size_t)Mrows * Dd];  // x split hi/lo
__device__ __align__(256) __nv_bfloat16 g_xl[(size_t)Mrows * Dd];
__device__ __align__(256) __nv_bfloat16 g_ah[(size_t)Mrows * Dd];  // attn out split
__device__ __align__(256) __nv_bfloat16 g_al[(size_t)Mrows * Dd];
__device__ __align__(256) __nv_bfloat16 g_wth[(size_t)K3 * K3];    // W^T concat [oc][kk]
__device__ __align__(256) __nv_bfloat16 g_wtl[(size_t)K3 * K3];
__device__ __align__(256) __nv_bfloat16 g_woh[(size_t)Dd * Dd];    // Wo^T [n][k]
__device__ __align__(256) __nv_bfloat16 g_wol[(size_t)Dd * Dd];

// ------------ small PTX helpers (plain-sm_103-safe) ------------
__device__ __forceinline__ uint32_t smem_u32(const void* p) {
    uint32_t a;
    asm("{ .reg .u64 t; cvta.to.shared.u64 t, %1; cvt.u32.u64 %0, t; }" : "=r"(a) : "l"(p));
    return a;
}
__device__ __forceinline__ void cp_async16(uint32_t saddr, const void* gaddr, uint32_t srcsize) {
    asm volatile("cp.async.cg.shared.global [%0], [%1], 16, %2;"
                 :: "r"(saddr), "l"(gaddr), "r"(srcsize) : "memory");
}
__device__ __forceinline__ void cp_commit() { asm volatile("cp.async.commit_group;" ::: "memory"); }
__device__ __forceinline__ void cp_wait0()  { asm volatile("cp.async.wait_group 0;" ::: "memory"); }
__device__ __forceinline__ void cp_wait1()  { asm volatile("cp.async.wait_group 1;" ::: "memory"); }

__device__ __forceinline__ void ldsm4(uint32_t* r, uint32_t addr) {
    asm volatile("ldmatrix.sync.aligned.m8n8.x4.shared.b16 {%0,%1,%2,%3}, [%4];"
                 : "=r"(r[0]), "=r"(r[1]), "=r"(r[2]), "=r"(r[3]) : "r"(addr));
}
__device__ __forceinline__ void mma16816(float* c, const uint32_t* a, const uint32_t* b) {
    asm volatile("mma.sync.aligned.m16n8k16.row.col.f32.bf16.bf16.f32 "
                 "{%0,%1,%2,%3}, {%4,%5,%6,%7}, {%8,%9}, {%0,%1,%2,%3};"
                 : "+f"(c[0]), "+f"(c[1]), "+f"(c[2]), "+f"(c[3])
                 : "r"(a[0]), "r"(a[1]), "r"(a[2]), "r"(a[3]), "r"(b[0]), "r"(b[1]));
}

// ============================================================
// precompute kernels
// ============================================================
__global__ void split_x(const float* __restrict__ x) {
    size_t i = (size_t)blockIdx.x * 256 + threadIdx.x;
    if (i >= (size_t)Mrows * Dd) return;
    float v = x[i];
    __nv_bfloat16 h = __float2bfloat16(v);
    g_xh[i] = h;
    g_xl[i] = __float2bfloat16(v - __bfloat162float(h));
}

__global__ void repack_w(const float* __restrict__ Wq,
                         const float* __restrict__ Wk,
                         const float* __restrict__ Wv) {
    size_t idx = (size_t)blockIdx.x * 256 + threadIdx.x;
    if (idx >= (size_t)K3 * K3) return;
    int oc = (int)(idx / K3);
    int kk = (int)(idx - (size_t)oc * K3);
    int t = kk >> 9, i = kk & 511;
    int p = oc >> 9, o = oc & 511;
    const float* W = (p == 0) ? Wq : (p == 1) ? Wk : Wv;
    float v = W[(size_t)o * K3 + i * 3 + t];
    __nv_bfloat16 h = __float2bfloat16(v);
    g_wth[idx] = h;
    g_wtl[idx] = __float2bfloat16(v - __bfloat162float(h));
}

__global__ void repack_wo(const float* __restrict__ Wo) {
    int idx = blockIdx.x * 256 + threadIdx.x;
    if (idx >= Dd * Dd) return;
    int n = idx >> 9, k = idx & 511;
    float v = Wo[(size_t)k * Dd + n];
    __nv_bfloat16 h = __float2bfloat16(v);
    g_woh[idx] = h;
    g_wol[idx] = __float2bfloat16(v - __bfloat162float(h));
}

// ============================================================
// warp-mma bf16 GEMM: C = A * B^T (B stored [N x K]); bf16x3 split.
// MODE 1: A gathered via im2col of x.
// CTA 128x128, 256 thr (8 warps, 2x4), warp tile 64x32, BK=32,
// double-buffered cp.async.  __launch_bounds__(256,2) -> 2 CTAs/SM
// (per-ma A-fragment loading keeps live regs under the 128 cap).
// smem rows: 32 data + 8 pad = 40 elems (80B) -> conflict-free ldmatrix.
// ============================================================
#define LDS_E 40
#define TILE_E (128 * LDS_E)
#define TILE_BYTES (TILE_E * 2)          // 10240 B
#define STAGE_BYTES (4 * TILE_BYTES)     // 40960 B
#define GEMM_SMEM (2 * STAGE_BYTES)      // 81920 B

template<int MODE, bool BIAS>
__global__ __launch_bounds__(256, 2)
void tc_gemm(const __nv_bfloat16* __restrict__ Ah, const __nv_bfloat16* __restrict__ Al,
             const __nv_bfloat16* __restrict__ Bh, const __nv_bfloat16* __restrict__ Bl,
             float* __restrict__ C, const float* __restrict__ bias, int K, int N)
{
    extern __shared__ __nv_bfloat16 smem[];
    const uint32_t sb = smem_u32(smem);
    const int tid = threadIdx.x;
    const int wid = tid >> 5, lid = tid & 31;
    const int warp_m = wid >> 2;      // 0..1  (64 rows)
    const int warp_n = wid & 3;       // 0..3  (32 cols)
    const int m0 = blockIdx.y * 128, n0 = blockIdx.x * 128;
    const int NC = K >> 5;

    // stage loader: 4 tiles x 512 16B-chunks, 256 thr -> 8 chunks each
    auto load_stage = [&](int c) {
        const int buf = c & 1;
        const int kk0 = c << 5;
        uint32_t sbase = sb + (uint32_t)buf * STAGE_BYTES;
        #pragma unroll
        for (int it = 0; it < 2; it++) {
            int id = tid + it * 256;            // 0..511
            int r = id >> 2, q = id & 3;        // row, 16B quad
            uint32_t soff = (uint32_t)(r * LDS_E + q * 8) * 2;
            size_t aoff; uint32_t vsz = 16;
            if (MODE == 1) {
                int gm = m0 + r;
                int bb = gm / Nn, nn = gm - bb * Nn;
                int t = kk0 >> 9;
                int d = (kk0 & 511) + q * 8;
                int jj = nn + t - 1;
                if (jj < 0 || jj >= Nn) { vsz = 0; jj = 0; }
                aoff = ((size_t)(bb * Nn + jj) << 9) + d;
            } else {
                aoff = (size_t)(m0 + r) * K + kk0 + q * 8;
            }
            cp_async16(sbase + 0 * TILE_BYTES + soff, Ah + aoff, vsz);
            cp_async16(sbase + 1 * TILE_BYTES + soff, Al + aoff, vsz);
            size_t boff = (size_t)(n0 + r) * K + kk0 + q * 8;
            cp_async16(sbase + 2 * TILE_BYTES + soff, Bh + boff, 16);
            cp_async16(sbase + 3 * TILE_BYTES + soff, Bl + boff, 16);
        }
        cp_commit();
    };

    float acc[4][4][4];
    #pragma unroll
    for (int i = 0; i < 4; i++)
        #pragma unroll
        for (int j = 0; j < 4; j++)
            #pragma unroll
            for (int e = 0; e < 4; e++) acc[i][j][e] = 0.f;

    load_stage(0);

    // ldmatrix lane addressing (byte units within a [128][40] tile)
    const uint32_t a_row  = (uint32_t)(warp_m * 64 + (lid & 15));
    const uint32_t a_koff = (uint32_t)((lid >> 4) * 16);
    const uint32_t b_row  = (uint32_t)(warp_n * 32 + ((lid >> 4) * 8) + (lid & 7));
    const uint32_t b_koff = (uint32_t)(((lid >> 3) & 1) * 16);

    for (int c = 0; c < NC; c++) {
        if (c + 1 < NC) { load_stage(c + 1); cp_wait1(); }
        else            { cp_wait0(); }
        __syncthreads();

        const uint32_t sbase = sb + (uint32_t)(c & 1) * STAGE_BYTES;
        const uint32_t tAh = sbase + 0 * TILE_BYTES;
        const uint32_t tAl = sbase + 1 * TILE_BYTES;
        const uint32_t tBh = sbase + 2 * TILE_BYTES;
        const uint32_t tBl = sbase + 3 * TILE_BYTES;

        #pragma unroll
        for (int ks = 0; ks < 2; ks++) {
            const uint32_t kb = (uint32_t)(ks * 32);
            // B fragments for this k16-step (16 regs, live across ma loop)
            uint32_t fbh[2][4], fbl[2][4];
            #pragma unroll
            for (int nb = 0; nb < 2; nb++) {
                uint32_t bo = ((b_row + nb * 16) * LDS_E) * 2 + b_koff + kb;
                ldsm4(fbh[nb], tBh + bo);
                ldsm4(fbl[nb], tBl + bo);
            }
            // A fragments loaded per-ma (short live range -> fits 128 regs)
            #pragma unroll
            for (int ma = 0; ma < 4; ma++) {
                uint32_t fah[4], fal[4];
                uint32_t ao = ((a_row + ma * 16) * LDS_E) * 2 + a_koff + kb;
                ldsm4(fah, tAh + ao);
                ldsm4(fal, tAl + ao);
                #pragma unroll
                for (int na = 0; na < 4; na++) {
                    const uint32_t* bh = &fbh[na >> 1][(na & 1) * 2];
                    const uint32_t* bl = &fbl[na >> 1][(na & 1) * 2];
                    mma16816(acc[ma][na], fah, bh);
                    mma16816(acc[ma][na], fah, bl);
                    mma16816(acc[ma][na], fal, bh);
                }
            }
        }
        __syncthreads();
    }

    // ---- epilogue ----
    const int mrow = m0 + warp_m * 64 + (lid >> 2);
    const int ncol = n0 + warp_n * 32 + (lid & 3) * 2;
    #pragma unroll
    for (int ma = 0; ma < 4; ma++) {
        #pragma unroll
        for (int na = 0; na < 4; na++) {
            int cc = ncol + na * 8;
            float b0 = 0.f, b1 = 0.f;
            if (BIAS) { b0 = bias[cc]; b1 = bias[cc + 1]; }
            float2 v0 = make_float2(acc[ma][na][0] + b0, acc[ma][na][1] + b1);
            float2 v1 = make_float2(acc[ma][na][2] + b0, acc[ma][na][3] + b1);
            *(float2*)(C + (size_t)(mrow + ma * 16)     * N + cc) = v0;
            *(float2*)(C + (size_t)(mrow + ma * 16 + 8) * N + cc) = v1;
        }
    }
}

// ============================================================
// qp[b,n,h] = tanh(x @ Wqf + bqf) @ Wqp (dyn bias factorization)
// ============================================================
__global__ __launch_bounds__(64)
void qp_kernel(const float* __restrict__ x, const float* __restrict__ Wqf,
               const float* __restrict__ bqf, const float* __restrict__ Wqp)
{
    __shared__ float xs[8][512];
    __shared__ float qf[8][64];
    int m0 = blockIdx.x * 8;
    int tid = threadIdx.x;

    for (int i = tid; i < 8 * 512; i += 64)
        xs[i >> 9][i & 511] = x[(size_t)m0 * 512 + i];
    __syncthreads();

    float acc[8];
    float bq = bqf[tid];
    #pragma unroll
    for (int r = 0; r < 8; r++) acc[r] = bq;
    for (int i = 0; i < 512; i++) {
        float w = Wqf[i * 64 + tid];
        #pragma unroll
        for (int r = 0; r < 8; r++) acc[r] += xs[r][i] * w;
    }
    #pragma unroll
    for (int r = 0; r < 8; r++) qf[r][tid] = tanhf(acc[r]);
    __syncthreads();

    int r = tid >> 3, h = tid & 7;
    float a = 0.f;
    #pragma unroll
    for (int t = 0; t < 64; t++) a += qf[r][t] * Wqp[t * 8 + h];
    g_qp[(size_t)(m0 + r) * 8 + h] = a;
}

// ============================================================
// Fused LayerNorm+residual + attention, one block per batch b.
// ============================================================
#define LNROW 513
#define SM_BUF   (3 * Nn * LNROW)
#define SM_SC    (SM_BUF)
#define SM_REL   (SM_SC + Hh * Nn * Nn)
#define SM_QPH   (SM_REL + Hh * (2 * Nn - 1))
#define FUSED_SMEM_F (SM_QPH + Nn * Hh)
#define FUSED_SMEM (FUSED_SMEM_F * 4)

__global__ __launch_bounds__(512, 1)
void ln_attn_kernel(const float* __restrict__ xin,
                    const float* __restrict__ gq_g, const float* __restrict__ gq_b,
                    const float* __restrict__ gk_g, const float* __restrict__ gk_b,
                    const float* __restrict__ gv_g, const float* __restrict__ gv_b,
                    const float* __restrict__ rel_table,
                    const float* __restrict__ gsb,
                    const float* __restrict__ alpha_p,
                    const float* __restrict__ bqp)
{
    extern __shared__ float sm[];
    float* buf  = sm;                 // [3][20][513]
    float* sc   = sm + SM_SC;         // [8][20][20]
    float* relh = sm + SM_REL;        // [8][39]
    float* qph  = sm + SM_QPH;        // [20][8]

    const int b = blockIdx.x;
    const int tid = threadIdx.x;
    const int wid = tid >> 5, lid = tid & 31;

    for (int i = tid; i < 3 * Nn * Dd; i += 512) {
        int p = i / (Nn * Dd);
        int rem = i - p * Nn * Dd;
        int n = rem >> 9, d = rem & 511;
        buf[(p * Nn + n) * LNROW + d] =
            g_conv[(size_t)(b * Nn + n) * K3 + p * Dd + d];
    }
    if (tid < Hh * (2 * Nn - 1)) relh[tid] = rel_table[(tid % (2 * Nn - 1)) * Hh + (tid / (2 * Nn - 1))];
    else if (tid >= 480 && tid < 480 + Nn) {
        int n = tid - 480;
        #pragma unroll
        for (int h = 0; h < Hh; h++)
            qph[n * Hh + h] = g_qp[(size_t)(b * Nn + n) * Hh + h];
    }
    __syncthreads();

    for (int r = wid; r < 3 * Nn; r += 16) {
        int p = r / Nn, n = r - p * Nn;
        float* row = buf + r * LNROW;
        float s = 0.f, sq = 0.f;
        #pragma unroll
        for (int j = 0; j < 16; j++) {
            float v = row[lid + j * 32];
            s += v; sq += v * v;
        }
        #pragma unroll
        for (int o = 16; o > 0; o >>= 1) {
            s  += __shfl_xor_sync(0xffffffffu, s,  o);
            sq += __shfl_xor_sync(0xffffffffu, sq, o);
        }
        float mean = s * (1.f / 512.f);
        float var  = sq * (1.f / 512.f) - mean * mean;
        float rstd = rsqrtf(var + 1e-5f);
        const float* g  = (p == 0) ? gq_g : (p == 1) ? gk_g : gv_g;
        const float* be = (p == 0) ? gq_b : (p == 1) ? gk_b : gv_b;
        const float* xr = xin + (size_t)(b * Nn + n) * Dd;
        #pragma unroll
        for (int j = 0; j < 16; j++) {
            int d = lid + j * 32;
            row[d] = xr[d] + (row[d] - mean) * rstd * g[d] + be[d];
        }
    }
    __syncthreads();

    const float alpha = *alpha_p;
    const float* q = buf;
    const float* k = buf + Nn * LNROW;
    const float* v = buf + 2 * Nn * LNROW;
    for (int t = tid; t < Hh * Nn * Nn; t += 512) {
        int h = t / (Nn * Nn);
        int rem = t - h * Nn * Nn;
        int n = rem / Nn, m = rem - n * Nn;
        const float* qr = q + n * LNROW + h * 64;
        const float* kr = k + m * LNROW + h * 64;
        float a = 0.f;
        #pragma unroll
        for (int d = 0; d < 64; d++) a += qr[d] * kr[d];
        a = a * 0.125f
          + relh[h * (2 * Nn - 1) + n - m + Nn - 1]
          + alpha * gsb[(size_t)(h * Nn + n) * Nn + m]
          + (qph[n * Hh + h] - qph[m * Hh + h]) + bqp[h];
        sc[t] = a;
    }
    __syncthreads();

    if (tid < Hh * Nn) {
        float* row = sc + tid * Nn;
        float mx = -1e30f;
        #pragma unroll
        for (int m = 0; m < Nn; m++) mx = fmaxf(mx, row[m]);
        float s = 0.f;
        #pragma unroll
        for (int m = 0; m < Nn; m++) { float e = expf(row[m] - mx); row[m] = e; s += e; }
        float inv = 1.f / s;
        #pragma unroll
        for (int m = 0; m < Nn; m++) row[m] *= inv;
    }
    __syncthreads();

    for (int t = tid; t < Hh * Nn * 64; t += 512) {
        int hn = t >> 6, d = t & 63;
        int h = hn / Nn, n = hn - h * Nn;
        const float* ar = sc + (h * Nn + n) * Nn;
        const float* vb = v + h * 64 + d;
        float a = 0.f;
        #pragma unroll
        for (int m = 0; m < Nn; m++) a += ar[m] * vb[m * LNROW];
        size_t dst = (size_t)(b * Nn + n) * Dd + h * 64 + d;
        __nv_bfloat16 hi = __float2bfloat16(a);
        g_ah[dst] = hi;
        g_al[dst] = __float2bfloat16(a - __bfloat162float(hi));
    }
}

// ============================================================
// launch
// ============================================================
extern "C" void kernel_launch(void* const* d_in, const int* in_sizes, int n_in,
                              void* d_out, int out_size)
{
    const float* x         = (const float*)d_in[0];
    const float* Wq        = (const float*)d_in[1];
    const float* Wk        = (const float*)d_in[2];
    const float* Wv        = (const float*)d_in[3];
    const float* gq_g      = (const float*)d_in[4];
    const float* gq_b      = (const float*)d_in[5];
    const float* gk_g      = (const float*)d_in[6];
    const float* gk_b      = (const float*)d_in[7];
    const float* gv_g      = (const float*)d_in[8];
    const float* gv_b      = (const float*)d_in[9];
    const float* rel_table = (const float*)d_in[10];
    const float* gsb       = (const float*)d_in[11];
    const float* alpha     = (const float*)d_in[12];
    const float* Wqf       = (const float*)d_in[13];
    const float* bqf       = (const float*)d_in[14];
    const float* Wqp       = (const float*)d_in[15];
    const float* bqp       = (const float*)d_in[16];
    const float* Wo        = (const float*)d_in[17];
    const float* bo        = (const float*)d_in[18];

    cudaFuncSetAttribute(tc_gemm<1, false>, cudaFuncAttributeMaxDynamicSharedMemorySize, GEMM_SMEM);
    cudaFuncSetAttribute(tc_gemm<0, true>,  cudaFuncAttributeMaxDynamicSharedMemorySize, GEMM_SMEM);
    cudaFuncSetAttribute(ln_attn_kernel,    cudaFuncAttributeMaxDynamicSharedMemorySize, FUSED_SMEM);

    __nv_bfloat16 *pxh, *pxl, *pwth, *pwtl, *pah, *pal, *pwoh, *pwol;
    float *pConv;
    cudaGetSymbolAddress((void**)&pxh, g_xh);
    cudaGetSymbolAddress((void**)&pxl, g_xl);
    cudaGetSymbolAddress((void**)&pwth, g_wth);
    cudaGetSymbolAddress((void**)&pwtl, g_wtl);
    cudaGetSymbolAddress((void**)&pah, g_ah);
    cudaGetSymbolAddress((void**)&pal, g_al);
    cudaGetSymbolAddress((void**)&pwoh, g_woh);
    cudaGetSymbolAddress((void**)&pwol, g_wol);
    cudaGetSymbolAddress((void**)&pConv, g_conv);

    // 1. precompute bf16 hi/lo splits
    split_x<<<(Mrows * Dd + 255) / 256, 256>>>(x);
    repack_w<<<(K3 * K3 + 255) / 256, 256>>>(Wq, Wk, Wv);
    repack_wo<<<(Dd * Dd + 255) / 256, 256>>>(Wo);

    // 2. fused QKV conv as im2col GEMM
    {
        dim3 grid(K3 / 128, Mrows / 128);   // (12, 320)
        tc_gemm<1, false><<<grid, 256, GEMM_SMEM>>>(pxh, pxl, pwth, pwtl,
                                                    pConv, nullptr, K3, K3);
    }

    // 3. dynamic-bias projection qp
    qp_kernel<<<Mrows / 8, 64>>>(x, Wqf, bqf, Wqp);

    // 4. fused LN+residual + attention (per batch), emits bf16 hi/lo
    ln_attn_kernel<<<Bsz, 512, FUSED_SMEM>>>(x, gq_g, gq_b, gk_g, gk_b, gv_g, gv_b,
                                             rel_table, gsb, alpha, bqp);

    // 5. output projection: [40960 x 512] @ Wo + bo
    {
        dim3 grid(Dd / 128, Mrows / 128);   // (4, 320)
        tc_gemm<0, true><<<grid, 256, GEMM_SMEM>>>(pah, pal, pwoh, pwol,
                                                   (float*)d_out, bo, Dd, Dd);
    }
}